// round 15
// baseline (speedup 1.0000x reference)
#include <cuda_runtime.h>

// Chamfer distance via exact grid nearest-neighbor search, v3.
// v2 (82 us) spent ~30 us on 8 tiny kernel launches. v3 fuses the whole
// grid build into ONE kernel (one block per segment, counts/scan/masks in
// dynamic smem) and folds the final reduction into the query kernel via a
// ticket counter. 2 launches total.

#define BB 8
#define NN 8192
#define GRID 32
#define NC (GRID * GRID * GRID)        // 32768 cells per segment
#define NSEG 16                        // 2 target-sets x 8 batches
#define NPTS (2 * BB * NN)             // 131072
#define CS 0.5f
#define LO (-8.0f)
#define INVCS 2.0f
#define EPS 1e-5f
#define QBLOCKS (NPTS / 256)           // 512
#define FXS 4398046511104.0            // 2^42 fixed-point scale
#define PPT 8                          // points per build thread (8192/1024)

__device__ unsigned g_cell[NSEG][NC];           // start<<14 | cnt
__device__ unsigned g_mask[NSEG][GRID * GRID];  // z-occupancy per (x,y) column
__device__ float4   g_pts[NSEG][NN];            // cell-sorted (x,y,z,|p|^2)
__device__ unsigned long long g_isum;
__device__ unsigned g_done;                      // zero-init; self-resetting

__device__ __forceinline__ int cell_coord(float v) {
    int c = (int)floorf((v - LO) * INVCS);
    return min(GRID - 1, max(0, c));
}
__device__ __forceinline__ float axis_dist(float q, int i) {
    float lo = LO + i * CS;
    return fmaxf(0.0f, fmaxf(lo - q, q - (lo + CS)));
}

// ---- K1: fused build. One block per segment; 1024 threads. ----
// smem layout: cnt[NC] | scan[1024] | mask[1024]
#define BSMEM_BYTES ((NC + 1024 + 1024) * 4)

extern "C" __global__ __launch_bounds__(1024)
void knn_build(const float* __restrict__ pred, const float* __restrict__ gt) {
    extern __shared__ unsigned sbuf[];
    unsigned* scnt  = sbuf;
    unsigned* sscan = sbuf + NC;
    unsigned* smask = sbuf + NC + 1024;

    const int seg = blockIdx.x;
    const int tid = threadIdx.x;

    // zero smem (+ global accumulator, once)
#pragma unroll
    for (int k = 0; k < NC / 1024; k++) scnt[k * 1024 + tid] = 0u;
    smask[tid] = 0u;
    if (seg == 0 && tid == 0) g_isum = 0ull;
    __syncthreads();

    // load points, count into smem, build column masks
    const int t = seg >> 3, b = seg & 7;
    const float* src = (t == 0 ? gt : pred) + (long)b * NN * 3;
    float px[PPT], py[PPT], pz[PPT];
    int pc[PPT];
#pragma unroll
    for (int k = 0; k < PPT; k++) {
        int i = k * 1024 + tid;
        float x = src[i * 3 + 0], y = src[i * 3 + 1], z = src[i * 3 + 2];
        px[k] = x; py[k] = y; pz[k] = z;
        int c = ((cell_coord(x) << 5) | cell_coord(y)) << 5 | cell_coord(z);
        pc[k] = c;
        atomicAdd(&scnt[c], 1u);
        atomicOr(&smask[c >> 5], 1u << (c & 31));
    }
    __syncthreads();

    // prefix: each thread serially owns 32 consecutive cells
    const int base = tid * 32;
    unsigned run = 0;
#pragma unroll
    for (int k = 0; k < 32; k++) run += scnt[base + k];
    sscan[tid] = run;
    __syncthreads();
    for (int o = 1; o < 1024; o <<= 1) {           // Hillis-Steele
        unsigned v = (tid >= o) ? sscan[tid - o] : 0u;
        __syncthreads();
        sscan[tid] += v;
        __syncthreads();
    }
    unsigned start = sscan[tid] - run;

    // write packed cells; convert smem counts -> scatter cursors
#pragma unroll
    for (int k = 0; k < 32; k++) {
        unsigned cnt = scnt[base + k];
        g_cell[seg][base + k] = (start << 14) | cnt;
        scnt[base + k] = start;                    // exclusive ownership
        start += cnt;
    }
    g_mask[seg][tid] = smask[tid];
    __syncthreads();

    // scatter into cell order
#pragma unroll
    for (int k = 0; k < PPT; k++) {
        unsigned slot = atomicAdd(&scnt[pc[k]], 1u);
        g_pts[seg][slot] = make_float4(px[k], py[k], pz[k],
                                       px[k] * px[k] + py[k] * py[k] + pz[k] * pz[k]);
    }
}

__device__ __forceinline__ void scan_cell(int tseg, int c, float qx, float qy,
                                          float qz, float qw, float& best) {
    unsigned pc = g_cell[tseg][c];
    unsigned cn = pc & 16383u;
    unsigned st = pc >> 14;
    for (unsigned s = st; s < st + cn; s++) {
        float4 p = g_pts[tseg][s];
        float d = (qw + p.w) - 2.0f * (qx * p.x + qy * p.y + qz * p.z);
        best = fminf(best, d);
    }
}

// ---- K2: exact ring search + fused finalize ----
extern "C" __global__ __launch_bounds__(256)
void knn_query(float* __restrict__ out) {
    int idx = blockIdx.x * 256 + threadIdx.x;
    int qseg = idx >> 13, i = idx & 8191;
    int tseg = qseg ^ 8;
    float4 q = g_pts[qseg][i];
    float qx = q.x, qy = q.y, qz = q.z, qw = q.w;
    int ix = cell_coord(qx), iy = cell_coord(qy), iz = cell_coord(qz);

    float best = __int_as_float(0x7F800000);

    for (int r = 0; r < GRID; r++) {
        if (r >= 1) {
            float rb = (r - 1) * CS;
            if (rb * rb > best + EPS) break;
        }
        for (int dx = -r; dx <= r; dx++) {
            int xx = ix + dx;
            if ((unsigned)xx >= (unsigned)GRID) continue;
            float ax = axis_dist(qx, xx);
            float ax2 = ax * ax;
            if (ax2 > best + EPS) continue;
            bool xf = (dx == r) || (dx == -r);
            for (int dy = -r; dy <= r; dy++) {
                int yy = iy + dy;
                if ((unsigned)yy >= (unsigned)GRID) continue;
                float ay = axis_dist(qy, yy);
                float rxy = ax2 + ay * ay;
                if (rxy > best + EPS) continue;
                unsigned mask = g_mask[tseg][(xx << 5) | yy];
                if (!mask) continue;
                int cbase = (((xx << 5) | yy) << 5);
                if (xf || dy == r || dy == -r) {
                    int zlo = max(0, iz - r), zhi = min(GRID - 1, iz + r);
                    unsigned m = mask & (0xFFFFFFFFu << zlo)
                                      & (0xFFFFFFFFu >> (31 - zhi));
                    while (m) {
                        int zz = __ffs(m) - 1;
                        m &= m - 1;
                        float az = axis_dist(qz, zz);
                        if (rxy + az * az > best + EPS) continue;
                        scan_cell(tseg, cbase | zz, qx, qy, qz, qw, best);
                    }
                } else {
                    int zz = iz - r;
                    if (zz >= 0 && ((mask >> zz) & 1u)) {
                        float az = axis_dist(qz, zz);
                        if (rxy + az * az <= best + EPS)
                            scan_cell(tseg, cbase | zz, qx, qy, qz, qw, best);
                    }
                    zz = iz + r;
                    if (zz < GRID && ((mask >> zz) & 1u)) {
                        float az = axis_dist(qz, zz);
                        if (rxy + az * az <= best + EPS)
                            scan_cell(tseg, cbase | zz, qx, qy, qz, qw, best);
                    }
                }
            }
        }
    }

    // Order-independent fixed-point sum -> deterministic output.
    unsigned long long fx = (unsigned long long)((double)best * FXS + 0.5);
    __shared__ unsigned long long ss[256];
    ss[threadIdx.x] = fx;
    __syncthreads();
    for (int st = 128; st > 0; st >>= 1) {
        if (threadIdx.x < st) ss[threadIdx.x] += ss[threadIdx.x + st];
        __syncthreads();
    }
    if (threadIdx.x == 0) {
        atomicAdd(&g_isum, ss[0]);
        __threadfence();
        unsigned ticket = atomicAdd(&g_done, 1u);
        if (ticket == QBLOCKS - 1) {
            unsigned long long total = atomicAdd(&g_isum, 0ull);
            atomicExch(&g_done, 0u);               // reset for next replay
            out[0] = (float)((double)total / FXS / (double)(BB * NN));
        }
    }
}

extern "C" void kernel_launch(void* const* d_in, const int* in_sizes, int n_in,
                              void* d_out, int out_size) {
    const float* pred = (const float*)d_in[0];
    const float* gt   = (const float*)d_in[1];
    float* out = (float*)d_out;

    static int smem_set = 0;
    if (!smem_set) {
        cudaFuncSetAttribute(knn_build,
                             cudaFuncAttributeMaxDynamicSharedMemorySize,
                             BSMEM_BYTES);
        smem_set = 1;
    }

    knn_build<<<NSEG, 1024, BSMEM_BYTES>>>(pred, gt);
    knn_query<<<QBLOCKS, 256>>>(out);
}

// round 16
// speedup vs baseline: 1.0968x; 1.0968x over previous
#include <cuda_runtime.h>

// Chamfer distance via exact grid nearest-neighbor search, v4.
// = v2's split build (proven ~13us) + query with 4-way MLP-unrolled candidate
// scan, 128-thread blocks, fused ticket-counter finalize. 7 launches.

#define BB 8
#define NN 8192
#define GRID 32
#define NC (GRID * GRID * GRID)        // 32768 cells per segment
#define NSEG 16                        // 2 target-sets x 8 batches
#define NPTS (2 * BB * NN)             // 131072
#define CS 0.5f
#define LO (-8.0f)
#define INVCS 2.0f
#define EPS 1e-5f
#define NBLK (NC / 1024)               // 32 prefix blocks per segment
#define QT 128
#define QBLOCKS (NPTS / QT)            // 1024
#define FXS 4398046511104.0            // 2^42 fixed-point scale

__device__ unsigned g_cnt[NSEG][NC];
__device__ unsigned g_off[NSEG][NC];
__device__ unsigned g_bsum[NSEG][NBLK];
__device__ unsigned g_bsumx[NSEG][NBLK];
__device__ unsigned g_cell[NSEG][NC];            // start<<14 | cnt
__device__ unsigned g_mask[NSEG][GRID * GRID];   // z-occupancy per column
__device__ float4   g_pts[NSEG][NN];             // cell-sorted (x,y,z,|p|^2)
__device__ unsigned long long g_isum;
__device__ unsigned g_done;                       // zero-init; self-resetting

__device__ __forceinline__ int cell_coord(float v) {
    int c = (int)floorf((v - LO) * INVCS);
    return min(GRID - 1, max(0, c));
}
__device__ __forceinline__ float axis_dist(float q, int i) {
    float lo = LO + i * CS;
    return fmaxf(0.0f, fmaxf(lo - q, q - (lo + CS)));
}

// ---- K0: zero counts, masks, accumulator ----
__global__ void knn_zero() {
    unsigned idx = blockIdx.x * 1024u + threadIdx.x;
    if (idx < NSEG * NC) ((unsigned*)g_cnt)[idx] = 0u;
    else if (idx < NSEG * NC + NSEG * GRID * GRID)
        ((unsigned*)g_mask)[idx - NSEG * NC] = 0u;
    else if (idx == NSEG * NC + NSEG * GRID * GRID) g_isum = 0ull;
}

// ---- K1: count + column masks ----
__global__ __launch_bounds__(256)
void knn_count(const float* __restrict__ pred, const float* __restrict__ gt) {
    int idx = blockIdx.x * 256 + threadIdx.x;
    int t = idx >> 16, b = (idx >> 13) & 7, i = idx & 8191;
    const float* p = (t == 0 ? gt : pred) + ((long)(b * NN + i)) * 3;
    int ix = cell_coord(p[0]), iy = cell_coord(p[1]), iz = cell_coord(p[2]);
    int seg = t * 8 + b;
    atomicAdd(&g_cnt[seg][((ix << 5) | iy) << 5 | iz], 1u);
    atomicOr(&g_mask[seg][(ix << 5) | iy], 1u << iz);
}

// ---- K2: per-1024-cell-block exclusive prefix + block totals ----
__global__ __launch_bounds__(256)
void knn_prefix1() {
    const int seg = blockIdx.y, blk = blockIdx.x, tid = threadIdx.x;
    const int base = blk * 1024 + tid * 4;
    unsigned c0 = g_cnt[seg][base], c1 = g_cnt[seg][base + 1];
    unsigned c2 = g_cnt[seg][base + 2], c3 = g_cnt[seg][base + 3];
    unsigned e1 = c0, e2 = c0 + c1, e3 = e2 + c2;
    unsigned tsum = e3 + c3;
    __shared__ unsigned s[256];
    s[tid] = tsum;
    __syncthreads();
    for (int o = 1; o < 256; o <<= 1) {
        unsigned v = (tid >= o) ? s[tid - o] : 0u;
        __syncthreads();
        s[tid] += v;
        __syncthreads();
    }
    unsigned excl = s[tid] - tsum;
    g_off[seg][base]     = excl;
    g_off[seg][base + 1] = excl + e1;
    g_off[seg][base + 2] = excl + e2;
    g_off[seg][base + 3] = excl + e3;
    if (tid == 0) g_bsum[seg][blk] = s[255];
}

// ---- K3: scan 32 block totals per segment ----
__global__ void knn_prefix2() {
    const int seg = blockIdx.x, tid = threadIdx.x;   // 32 threads
    unsigned v = g_bsum[seg][tid];
    __shared__ unsigned s[32];
    s[tid] = v;
    __syncwarp();
    for (int o = 1; o < 32; o <<= 1) {
        unsigned u = (tid >= o) ? s[tid - o] : 0u;
        __syncwarp();
        s[tid] += u;
        __syncwarp();
    }
    g_bsumx[seg][tid] = s[tid] - v;
}

// ---- K4: pack per-cell (start, count) ----
__global__ __launch_bounds__(1024)
void knn_cellpack() {
    unsigned idx = blockIdx.x * 1024u + threadIdx.x;
    int seg = idx >> 15, c = idx & (NC - 1);
    unsigned start = g_off[seg][c] + g_bsumx[seg][c >> 10];
    g_cell[seg][c] = (start << 14) | g_cnt[seg][c];
}

// ---- K5: scatter points into cell order ----
__global__ __launch_bounds__(256)
void knn_scatter(const float* __restrict__ pred, const float* __restrict__ gt) {
    int idx = blockIdx.x * 256 + threadIdx.x;
    int t = idx >> 16, b = (idx >> 13) & 7, i = idx & 8191;
    int seg = t * 8 + b;
    const float* p = (t == 0 ? gt : pred) + ((long)(b * NN + i)) * 3;
    float x = p[0], y = p[1], z = p[2];
    int ix = cell_coord(x), iy = cell_coord(y), iz = cell_coord(z);
    int c = ((ix << 5) | iy) << 5 | iz;
    unsigned local = atomicAdd(&g_off[seg][c], 1u);
    g_pts[seg][local + g_bsumx[seg][c >> 10]] =
        make_float4(x, y, z, x * x + y * y + z * z);
}

// Candidate scan, 4-way unrolled for MLP (4 outstanding LDG.128 per lane).
__device__ __forceinline__ void scan_cell(int tseg, int c, float qx, float qy,
                                          float qz, float qw, float& best) {
    unsigned pc = g_cell[tseg][c];
    unsigned cn = pc & 16383u;
    if (!cn) return;
    unsigned s = pc >> 14;
    unsigned end = s + cn;
    const float4* pts = g_pts[tseg];
    float b0 = best, b1 = best, b2 = best, b3 = best;
    for (; s + 4 <= end; s += 4) {
        float4 p0 = pts[s], p1 = pts[s + 1], p2 = pts[s + 2], p3 = pts[s + 3];
        b0 = fminf(b0, (qw + p0.w) - 2.0f * (qx * p0.x + qy * p0.y + qz * p0.z));
        b1 = fminf(b1, (qw + p1.w) - 2.0f * (qx * p1.x + qy * p1.y + qz * p1.z));
        b2 = fminf(b2, (qw + p2.w) - 2.0f * (qx * p2.x + qy * p2.y + qz * p2.z));
        b3 = fminf(b3, (qw + p3.w) - 2.0f * (qx * p3.x + qy * p3.y + qz * p3.z));
    }
    for (; s < end; s++) {
        float4 p = pts[s];
        b0 = fminf(b0, (qw + p.w) - 2.0f * (qx * p.x + qy * p.y + qz * p.z));
    }
    best = fminf(fminf(b0, b1), fminf(b2, b3));
}

// ---- K6: exact ring search + fused finalize ----
__global__ __launch_bounds__(QT)
void knn_query(float* __restrict__ out) {
    int idx = blockIdx.x * QT + threadIdx.x;
    int qseg = idx >> 13, i = idx & 8191;
    int tseg = qseg ^ 8;
    float4 q = g_pts[qseg][i];
    float qx = q.x, qy = q.y, qz = q.z, qw = q.w;
    int ix = cell_coord(qx), iy = cell_coord(qy), iz = cell_coord(qz);

    float best = __int_as_float(0x7F800000);

    for (int r = 0; r < GRID; r++) {
        if (r >= 1) {
            float rb = (r - 1) * CS;
            if (rb * rb > best + EPS) break;
        }
        for (int dx = -r; dx <= r; dx++) {
            int xx = ix + dx;
            if ((unsigned)xx >= (unsigned)GRID) continue;
            float ax = axis_dist(qx, xx);
            float ax2 = ax * ax;
            if (ax2 > best + EPS) continue;
            bool xf = (dx == r) || (dx == -r);
            for (int dy = -r; dy <= r; dy++) {
                int yy = iy + dy;
                if ((unsigned)yy >= (unsigned)GRID) continue;
                float ay = axis_dist(qy, yy);
                float rxy = ax2 + ay * ay;
                if (rxy > best + EPS) continue;
                unsigned mask = g_mask[tseg][(xx << 5) | yy];
                if (!mask) continue;
                int cbase = (((xx << 5) | yy) << 5);
                if (xf || dy == r || dy == -r) {
                    int zlo = max(0, iz - r), zhi = min(GRID - 1, iz + r);
                    unsigned m = mask & (0xFFFFFFFFu << zlo)
                                      & (0xFFFFFFFFu >> (31 - zhi));
                    while (m) {
                        int zz = __ffs(m) - 1;
                        m &= m - 1;
                        float az = axis_dist(qz, zz);
                        if (rxy + az * az > best + EPS) continue;
                        scan_cell(tseg, cbase | zz, qx, qy, qz, qw, best);
                    }
                } else {
                    int zz = iz - r;
                    if (zz >= 0 && ((mask >> zz) & 1u)) {
                        float az = axis_dist(qz, zz);
                        if (rxy + az * az <= best + EPS)
                            scan_cell(tseg, cbase | zz, qx, qy, qz, qw, best);
                    }
                    zz = iz + r;
                    if (zz < GRID && ((mask >> zz) & 1u)) {
                        float az = axis_dist(qz, zz);
                        if (rxy + az * az <= best + EPS)
                            scan_cell(tseg, cbase | zz, qx, qy, qz, qw, best);
                    }
                }
            }
        }
    }

    // Order-independent fixed-point sum -> deterministic output.
    unsigned long long fx = (unsigned long long)((double)best * FXS + 0.5);
    __shared__ unsigned long long ss[QT];
    ss[threadIdx.x] = fx;
    __syncthreads();
    for (int st = QT / 2; st > 0; st >>= 1) {
        if (threadIdx.x < st) ss[threadIdx.x] += ss[threadIdx.x + st];
        __syncthreads();
    }
    if (threadIdx.x == 0) {
        atomicAdd(&g_isum, ss[0]);
        __threadfence();
        unsigned ticket = atomicAdd(&g_done, 1u);
        if (ticket == QBLOCKS - 1) {
            unsigned long long total = atomicAdd(&g_isum, 0ull);
            atomicExch(&g_done, 0u);               // reset for next replay
            out[0] = (float)((double)total / FXS / (double)(BB * NN));
        }
    }
}

extern "C" void kernel_launch(void* const* d_in, const int* in_sizes, int n_in,
                              void* d_out, int out_size) {
    const float* pred = (const float*)d_in[0];
    const float* gt   = (const float*)d_in[1];
    float* out = (float*)d_out;

    int zero_elems = NSEG * NC + NSEG * GRID * GRID + 1;
    knn_zero<<<(zero_elems + 1023) / 1024, 1024>>>();
    knn_count<<<NPTS / 256, 256>>>(pred, gt);
    knn_prefix1<<<dim3(NBLK, NSEG), 256>>>();
    knn_prefix2<<<NSEG, 32>>>();
    knn_cellpack<<<(NSEG * NC) / 1024, 1024>>>();
    knn_scatter<<<NPTS / 256, 256>>>(pred, gt);
    knn_query<<<QBLOCKS, QT>>>(out);
}